// round 14
// baseline (speedup 1.0000x reference)
#include <cuda_runtime.h>
#include <cuda_fp16.h>
#include <cstdint>
#include <math.h>

#define B_SZ   4
#define S_LEN  2048
#define NH     16
#define HD     128
#define DM     2048
#define M_TOT  (B_SZ * S_LEN)
typedef __half hf;

// ---------------- scratch (device globals; allocation-free) ----------------
__device__ __align__(128) hf g_xh[(size_t)M_TOT * DM];
__device__ __align__(128) hf g_qh[(size_t)M_TOT * DM];
__device__ __align__(128) hf g_kh[(size_t)M_TOT * DM];
__device__ __align__(128) hf g_vh[(size_t)M_TOT * DM];
__device__ __align__(128) hf g_ah[(size_t)M_TOT * DM];
__device__ __align__(128) hf g_wh[4][(size_t)DM * DM];   // [wq;wk;wv;wo], [N,K] fp16

// ---------------- helpers ----------------
__device__ __forceinline__ uint32_t smem_u32(const void* p) {
    uint32_t a;
    asm("{ .reg .u64 t; cvta.to.shared.u64 t, %1; cvt.u32.u64 %0, t; }"
        : "=r"(a) : "l"(p));
    return a;
}
__device__ __forceinline__ uint32_t pack_h2f(float a, float b) {
    __half2 t = __floats2half2_rn(a, b);
    return *reinterpret_cast<uint32_t*>(&t);
}

#define MMAH(d, a0, a1, a2, a3, b0, b1)                                      \
    asm volatile(                                                            \
        "mma.sync.aligned.m16n8k16.row.col.f32.f16.f16.f32 "                 \
        "{%0,%1,%2,%3}, {%4,%5,%6,%7}, {%8,%9}, {%0,%1,%2,%3};"              \
        : "+f"((d)[0]), "+f"((d)[1]), "+f"((d)[2]), "+f"((d)[3])             \
        : "r"(a0), "r"(a1), "r"(a2), "r"(a3), "r"(b0), "r"(b1))

#define LDMX4(r0, r1, r2, r3, addr)                                          \
    asm volatile("ldmatrix.sync.aligned.m8n8.x4.shared.b16 "                 \
        "{%0,%1,%2,%3}, [%4];"                                               \
        : "=r"(r0), "=r"(r1), "=r"(r2), "=r"(r3) : "r"(addr))

#define LDMX4T(r0, r1, r2, r3, addr)                                         \
    asm volatile("ldmatrix.sync.aligned.m8n8.x4.trans.shared.b16 "           \
        "{%0,%1,%2,%3}, [%4];"                                               \
        : "=r"(r0), "=r"(r1), "=r"(r2), "=r"(r3) : "r"(addr))

#define CP16(dst, src)                                                       \
    asm volatile("cp.async.cg.shared.global [%0], [%1], 16;"                 \
                 :: "r"(dst), "l"(src))
#define CP_COMMIT() asm volatile("cp.async.commit_group;" ::)
#define CP_WAIT(n)  asm volatile("cp.async.wait_group %0;" :: "n"(n))

// ---------------------------------------------------------------------------
// x: fp32 -> single fp16
// ---------------------------------------------------------------------------
__global__ __launch_bounds__(256) void convert_x(
    const float* __restrict__ in, hf* __restrict__ H)
{
    size_t base = ((size_t)blockIdx.x * 256 + threadIdx.x) * 8;
    float4 v0 = *(const float4*)(in + base);
    float4 v1 = *(const float4*)(in + base + 4);
    uint4 hv;
    hv.x = pack_h2f(v0.x, v0.y); hv.y = pack_h2f(v0.z, v0.w);
    hv.z = pack_h2f(v1.x, v1.y); hv.w = pack_h2f(v1.z, v1.w);
    *(uint4*)(H + base) = hv;
}

// ---------------------------------------------------------------------------
// All 4 weights: [K,N] fp32 -> [N,K] fp16 in one launch (z = weight index)
// ---------------------------------------------------------------------------
__global__ __launch_bounds__(256) void transpose_convert4(
    const float* __restrict__ w0, const float* __restrict__ w1,
    const float* __restrict__ w2, const float* __restrict__ w3,
    hf* __restrict__ Hbase)
{
    __shared__ float t[32][33];
    const int z = blockIdx.z;
    const float* in = (z == 0) ? w0 : (z == 1) ? w1 : (z == 2) ? w2 : w3;
    hf* H = Hbase + (size_t)z * DM * DM;

    int x = blockIdx.x * 32 + threadIdx.x;
    int y = blockIdx.y * 32 + threadIdx.y;
    #pragma unroll
    for (int i = 0; i < 4; i++)
        t[threadIdx.y + i * 8][threadIdx.x] = in[(size_t)(y + i * 8) * DM + x];
    __syncthreads();
    x = blockIdx.y * 32 + threadIdx.x;
    y = blockIdx.x * 32 + threadIdx.y;
    #pragma unroll
    for (int i = 0; i < 4; i++)
        H[(size_t)(y + i * 8) * DM + x] =
            __float2half_rn(t[threadIdx.x][threadIdx.y + i * 8]);
}

// ---------------------------------------------------------------------------
// RoPE epilogue helper
// ---------------------------------------------------------------------------
__device__ __forceinline__ void rope_pair(
    int row, int col, float& v0, float& v1, float scale)
{
    int s = row & (S_LEN - 1);
    int i = (col & (HD - 1)) >> 1;
    float fraction  = (2.0f * (float)i) / (float)HD;
    float timescale = exp2f(fraction * 13.287712379549449f); // log2(10000)
    float ang = (float)s / timescale;
    float sv, cv;
    sincosf(ang, &sv, &cv);
    float r0 = (v0 * cv - v1 * sv) * scale;
    float r1 = (v1 * cv + v0 * sv) * scale;
    v0 = r0; v1 = r1;
}

// ---------------------------------------------------------------------------
// GEMM v4: 128x128 CTA tile, 4 warps (128 thr), warp tile 64x64.
// 64 MMAs : 16 ldmatrix per warp-chunk. 3-stage cp.async, 2 CTAs/SM.
// FUSED=1: B = stacked qkv weights, RoPE epilogue. FUSED=0: fp32 out.
// ---------------------------------------------------------------------------
#define GSTR   40
#define GA_EL  (128 * GSTR)
#define G1_STAGE_BYTES (2 * GA_EL * 2)          // 20480
#define GEMM1_SMEM (3 * G1_STAGE_BYTES)         // 61440

template<int FUSED>
__global__ __launch_bounds__(128, 2) void gemm_w64(
    const hf* __restrict__ A, const hf* __restrict__ B,
    hf* __restrict__ Q, hf* __restrict__ Kout, hf* __restrict__ V,
    float* __restrict__ Cf, int M, int K)
{
    extern __shared__ __align__(16) char gsm[];
    const uint32_t sb = smem_u32(gsm);

    const int tid  = threadIdx.x;
    const int lane = tid & 31;
    const int wid  = tid >> 5;          // 0..3
    const int warpM = wid & 1;          // 2 along M
    const int warpN = wid >> 1;         // 2 along N
    const int n0 = blockIdx.x * 128;
    const int m0 = blockIdx.y * 128;

    const int lm = lane & 15, lh = lane >> 4;
    const int kb_row    = (lane >> 4) * 8 + (lane & 7);
    const int kb_coladd = ((lane >> 3) & 1) * 8;

    float acc[4][8][4];                 // mt x nt x frag
    #pragma unroll
    for (int mt = 0; mt < 4; mt++)
        #pragma unroll
        for (int nt = 0; nt < 8; nt++)
            #pragma unroll
            for (int e = 0; e < 4; e++) acc[mt][nt][e] = 0.f;

    const int NK = K / 32;

    // loader: thread = row; 4 chunks of 16B per array
    auto issue_stage = [&](int kt) {
        const uint32_t sbase = sb + (uint32_t)(kt % 3) * G1_STAGE_BYTES;
        const size_t abase = (size_t)(m0 + tid) * K + kt * 32;
        const size_t bbase = (size_t)(n0 + tid) * K + kt * 32;
        #pragma unroll
        for (int ch = 0; ch < 4; ch++) {
            uint32_t doff = (uint32_t)(tid * GSTR + ch * 8) * 2;
            CP16(sbase + doff,             A + abase + ch * 8);
            CP16(sbase + GA_EL * 2 + doff, B + bbase + ch * 8);
        }
        CP_COMMIT();
    };

    issue_stage(0);
    issue_stage(1);

    for (int kt = 0; kt < NK; kt++) {
        if (kt + 1 < NK) CP_WAIT(1); else CP_WAIT(0);
        __syncthreads();
        if (kt + 2 < NK) issue_stage(kt + 2);

        const uint32_t sbase = sb + (uint32_t)(kt % 3) * G1_STAGE_BYTES;
        #pragma unroll
        for (int kc = 0; kc < 2; kc++) {
            uint32_t ah[4][4], bh[4][4];
            #pragma unroll
            for (int mt = 0; mt < 4; mt++) {
                uint32_t aaddr = sbase +
                    (uint32_t)((warpM * 64 + mt * 16 + lm) * GSTR + kc * 16 + lh * 8) * 2;
                LDMX4(ah[mt][0], ah[mt][1], ah[mt][2], ah[mt][3], aaddr);
            }
            #pragma unroll
            for (int ng = 0; ng < 4; ng++) {
                uint32_t baddr = sbase + GA_EL * 2 +
                    (uint32_t)((warpN * 64 + ng * 16 + kb_row) * GSTR + kc * 16 + kb_coladd) * 2;
                LDMX4(bh[ng][0], bh[ng][1], bh[ng][2], bh[ng][3], baddr);
            }
            #pragma unroll
            for (int mt = 0; mt < 4; mt++)
                #pragma unroll
                for (int nt = 0; nt < 8; nt++) {
                    const int ng = nt >> 1, o = (nt & 1) * 2;
                    MMAH(acc[mt][nt], ah[mt][0], ah[mt][1], ah[mt][2], ah[mt][3],
                         bh[ng][o], bh[ng][o + 1]);
                }
        }
    }

    const int mrow = lane >> 2;
    const int kcol = (lane & 3) * 2;    // even -> (col, col+1) is a RoPE pair
    if (FUSED) {
        const int which = blockIdx.x >> 4;    // 0=q, 1=k, 2=v
        hf* Ch = (which == 0) ? Q : (which == 1) ? Kout : V;
        const float qs = (which == 0) ? 0.08838834764831845f : 1.0f;
        const bool rope = (which < 2);
        #pragma unroll
        for (int mt = 0; mt < 4; mt++) {
            #pragma unroll
            for (int nt = 0; nt < 8; nt++) {
                int row = m0 + warpM * 64 + mt * 16 + mrow;
                int col = n0 + warpN * 64 + nt * 8 + kcol;
                float v0 = acc[mt][nt][0], v1 = acc[mt][nt][1];
                float v2 = acc[mt][nt][2], v3 = acc[mt][nt][3];
                if (rope) {
                    rope_pair(row,     col, v0, v1, qs);
                    rope_pair(row + 8, col, v2, v3, qs);
                }
                int cl = col & (DM - 1);
                *(uint32_t*)(Ch + (size_t)row * DM + cl)       = pack_h2f(v0, v1);
                *(uint32_t*)(Ch + (size_t)(row + 8) * DM + cl) = pack_h2f(v2, v3);
            }
        }
    } else {
        #pragma unroll
        for (int mt = 0; mt < 4; mt++) {
            #pragma unroll
            for (int nt = 0; nt < 8; nt++) {
                int row = m0 + warpM * 64 + mt * 16 + mrow;
                int col = n0 + warpN * 64 + nt * 8 + kcol;
                *(float2*)(Cf + (size_t)row * DM + col) =
                    make_float2(acc[mt][nt][0], acc[mt][nt][1]);
                *(float2*)(Cf + (size_t)(row + 8) * DM + col) =
                    make_float2(acc[mt][nt][2], acc[mt][nt][3]);
            }
        }
    }
}

// ---------------------------------------------------------------------------
// Flash attention (R12 version, 282us known-good): 128-row q tiles, 8 warps.
// ---------------------------------------------------------------------------
#define FSTR    136
#define F_Q     0
#define F_KV0   (128 * FSTR)
#define F_KVSZ  (2 * 64 * FSTR)
#define V_OFF   (64 * FSTR)
#define FLASH_SMEM_BYTES ((F_KV0 + 2 * F_KVSZ) * 2)   // 104448

__global__ __launch_bounds__(256, 1) void flash_tc5(
    const hf* __restrict__ Qh, const hf* __restrict__ Kh,
    const hf* __restrict__ Vh, hf* __restrict__ Oh)
{
    extern __shared__ __align__(16) char fsm[];
    const uint32_t sb = smem_u32(fsm);

    const int tid  = threadIdx.x;
    const int lane = tid & 31;
    const int w    = tid >> 5;
    const int qt   = blockIdx.x;
    const int hN   = blockIdx.y;
    const int b    = blockIdx.z;
    const int q0   = qt * 128;
    const size_t head = (size_t)hN * HD;

    auto issue_kv = [&](int kt, int st) {
        const int k0 = kt * 64;
        const uint32_t base = sb + (F_KV0 + st * F_KVSZ) * 2;
        #pragma unroll
        for (int i = 0; i < 4; i++) {
            int idx = tid + i * 256;
            int row = idx >> 4, ch = idx & 15;
            uint32_t doff = (uint32_t)(row * FSTR + ch * 8) * 2;
            size_t g = ((size_t)(b * S_LEN + k0 + row)) * DM + head + ch * 8;
            CP16(base + doff,             Kh + g);
            CP16(base + V_OFF * 2 + doff, Vh + g);
        }
        CP_COMMIT();
    };

    #pragma unroll
    for (int i = 0; i < 8; i++) {
        int idx = tid + i * 256;
        int row = idx >> 4, ch = idx & 15;
        uint32_t doff = (uint32_t)(row * FSTR + ch * 8) * 2;
        size_t g = ((size_t)(b * S_LEN + q0 + row)) * DM + head + ch * 8;
        CP16(sb + doff, Qh + g);
    }
    issue_kv(0, 0);

    float m0 = -1e30f, m1 = -1e30f, l0 = 0.f, l1 = 0.f;
    float o[16][4];
    #pragma unroll
    for (int t = 0; t < 16; t++)
        #pragma unroll
        for (int e = 0; e < 4; e++) o[t][e] = 0.f;

    const int ktiles = 2 * qt + 2;

    const uint32_t qa_base =
        sb + ((w * 16 + (lane & 15)) * FSTR + (lane >> 4) * 8) * 2;
    const uint32_t kb_row    = (lane >> 4) * 8 + (lane & 7);
    const uint32_t kb_coladd = ((lane >> 3) & 1) * 8;
    const uint32_t vb_rowadd = ((lane >> 3) & 1) * 8 + (lane & 7);
    const uint32_t vb_coladd = (lane >> 4) * 8;

    for (int kt = 0; kt < ktiles; kt++) {
        const int st = kt & 1;
        CP_WAIT(0);
        __syncthreads();
        if (kt + 1 < ktiles) issue_kv(kt + 1, st ^ 1);

        const uint32_t khb = F_KV0 + st * F_KVSZ;
        const uint32_t vhb = khb + V_OFF;

        float c[8][4];
        #pragma unroll
        for (int t = 0; t < 8; t++)
            #pragma unroll
            for (int e = 0; e < 4; e++) c[t][e] = 0.f;

        #pragma unroll
        for (int kc = 0; kc < 8; kc++) {
            uint32_t a0, a1, a2, a3;
            LDMX4(a0, a1, a2, a3, qa_base + kc * 32);
            #pragma unroll
            for (int tp = 0; tp < 4; tp++) {
                uint32_t b0, b1, b2, b3;
                uint32_t kaddr = sb +
                    (khb + (tp * 16 + kb_row) * FSTR + kc * 16 + kb_coladd) * 2;
                LDMX4(b0, b1, b2, b3, kaddr);
                MMAH(c[2*tp],   a0, a1, a2, a3, b0, b1);
                MMAH(c[2*tp+1], a0, a1, a2, a3, b2, b3);
            }
        }

        const int rowg0 = q0 + w * 16 + (lane >> 2);
        if (kt >= 2 * qt) {
            const int k0 = kt * 64;
            #pragma unroll
            for (int t = 0; t < 8; t++) {
                int colb = k0 + t * 8 + (lane & 3) * 2;
                if (colb     > rowg0)     c[t][0] = -1e30f;
                if (colb + 1 > rowg0)     c[t][1] = -1e30f;
                if (colb     > rowg0 + 8) c[t][2] = -1e30f;
                if (colb + 1 > rowg0 + 8) c[t][3] = -1e30f;
            }
        }

        float mx0 = -1e30f, mx1 = -1e30f;
        #pragma unroll
        for (int t = 0; t < 8; t++) {
            mx0 = fmaxf(mx0, fmaxf(c[t][0], c[t][1]));
            mx1 = fmaxf(mx1, fmaxf(c[t][2], c[t][3]));
        }
        mx0 = fmaxf(mx0, __shfl_xor_sync(0xffffffffu, mx0, 1));
        mx0 = fmaxf(mx0, __shfl_xor_sync(0xffffffffu, mx0, 2));
        mx1 = fmaxf(mx1, __shfl_xor_sync(0xffffffffu, mx1, 1));
        mx1 = fmaxf(mx1, __shfl_xor_sync(0xffffffffu, mx1, 2));
        const float mn0 = fmaxf(m0, mx0);
        const float mn1 = fmaxf(m1, mx1);
        const float sc0 = __expf(m0 - mn0);
        const float sc1 = __expf(m1 - mn1);
        float sum0 = 0.f, sum1 = 0.f;
        #pragma unroll
        for (int t = 0; t < 8; t++) {
            c[t][0] = __expf(c[t][0] - mn0); sum0 += c[t][0];
            c[t][1] = __expf(c[t][1] - mn0); sum0 += c[t][1];
            c[t][2] = __expf(c[t][2] - mn1); sum1 += c[t][2];
            c[t][3] = __expf(c[t][3] - mn1); sum1 += c[t][3];
        }
        sum0 += __shfl_xor_sync(0xffffffffu, sum0, 1);
        sum0 += __shfl_xor_sync(0xffffffffu, sum0, 2);
        sum1 += __shfl_xor_sync(0xffffffffu, sum1, 1);
        sum1 += __shfl_xor_sync(0xffffffffu, sum1, 2);
        m0 = mn0; m1 = mn1;
        l0 = l0 * sc0 + sum0;
        l1 = l1 * sc1 + sum1;
        #pragma unroll
        for (int t = 0; t < 16; t++) {
            o[t][0] *= sc0; o[t][1] *= sc0;
            o[t][2] *= sc1; o[t][3] *= sc1;
        }

        #pragma unroll
        for (int kc = 0; kc < 4; kc++) {
            uint32_t pa[4];
            #pragma unroll
            for (int half = 0; half < 2; half++) {
                const int t = 2 * kc + half;
                pa[2*half]   = pack_h2f(c[t][0], c[t][1]);
                pa[2*half+1] = pack_h2f(c[t][2], c[t][3]);
            }
            #pragma unroll
            for (int tp = 0; tp < 8; tp++) {
                uint32_t v0, v1, v2, v3;
                uint32_t vaddr = sb +
                    (vhb + (kc * 16 + vb_rowadd) * FSTR + tp * 16 + vb_coladd) * 2;
                LDMX4T(v0, v1, v2, v3, vaddr);
                MMAH(o[2*tp],   pa[0], pa[1], pa[2], pa[3], v0, v1);
                MMAH(o[2*tp+1], pa[0], pa[1], pa[2], pa[3], v2, v3);
            }
        }
    }

    const float inv0 = 1.0f / l0;
    const float inv1 = 1.0f / l1;
    const int rowg = q0 + w * 16 + (lane >> 2);
    #pragma unroll
    for (int t = 0; t < 16; t++) {
        size_t g0 = ((size_t)(b * S_LEN + rowg)) * DM + head + t * 8 + (lane & 3) * 2;
        size_t g1 = g0 + 8 * DM;
        *(uint32_t*)(Oh + g0) = pack_h2f(o[t][0] * inv0, o[t][1] * inv0);
        *(uint32_t*)(Oh + g1) = pack_h2f(o[t][2] * inv1, o[t][3] * inv1);
    }
}

// ---------------------------------------------------------------------------
extern "C" void kernel_launch(void* const* d_in, const int* in_sizes, int n_in,
                              void* d_out, int out_size)
{
    const float* x  = (const float*)d_in[0];
    const float* wq = (const float*)d_in[1];
    const float* wk = (const float*)d_in[2];
    const float* wv = (const float*)d_in[3];
    const float* wo = (const float*)d_in[4];
    float* out = (float*)d_out;

    hf *xh, *qh, *kh, *vh, *ah, *wh;
    cudaGetSymbolAddress((void**)&xh, g_xh);
    cudaGetSymbolAddress((void**)&qh, g_qh);
    cudaGetSymbolAddress((void**)&kh, g_kh);
    cudaGetSymbolAddress((void**)&vh, g_vh);
    cudaGetSymbolAddress((void**)&ah, g_ah);
    cudaGetSymbolAddress((void**)&wh, g_wh);
    const size_t WSZ = (size_t)DM * DM;

    convert_x<<<(M_TOT * (size_t)DM) / (256 * 8), 256>>>(x, xh);
    dim3 tgrid(DM / 32, DM / 32, 4), tblk(32, 8);
    transpose_convert4<<<tgrid, tblk>>>(wq, wk, wv, wo, wh);

    cudaFuncSetAttribute(gemm_w64<0>, cudaFuncAttributeMaxDynamicSharedMemorySize,
                         GEMM1_SMEM);
    cudaFuncSetAttribute(gemm_w64<1>, cudaFuncAttributeMaxDynamicSharedMemorySize,
                         GEMM1_SMEM);

    // Fused QKV projection + RoPE epilogue: N = 3*2048, one launch
    dim3 qkvgrid(3 * DM / 128, M_TOT / 128);
    gemm_w64<1><<<qkvgrid, 128, GEMM1_SMEM>>>(xh, wh, qh, kh, vh, nullptr,
                                              M_TOT, DM);

    cudaFuncSetAttribute(flash_tc5, cudaFuncAttributeMaxDynamicSharedMemorySize,
                         FLASH_SMEM_BYTES);
    dim3 fgrid(S_LEN / 128, NH, B_SZ);
    flash_tc5<<<fgrid, 256, FLASH_SMEM_BYTES>>>(qh, kh, vh, ah);

    // Out-proj: fp32 output
    dim3 ogrid(DM / 128, M_TOT / 128);
    gemm_w64<0><<<ogrid, 128, GEMM1_SMEM>>>(ah, wh + 3 * WSZ, nullptr, nullptr,
                                            nullptr, out, M_TOT, DM);
}

// round 15
// speedup vs baseline: 1.2192x; 1.2192x over previous
#include <cuda_runtime.h>
#include <cuda_fp16.h>
#include <cstdint>
#include <math.h>

#define B_SZ   4
#define S_LEN  2048
#define NH     16
#define HD     128
#define DM     2048
#define M_TOT  (B_SZ * S_LEN)
typedef __half hf;

// ---------------- scratch (device globals; allocation-free) ----------------
__device__ __align__(128) hf g_xh[(size_t)M_TOT * DM];
__device__ __align__(128) hf g_qh[(size_t)M_TOT * DM];
__device__ __align__(128) hf g_kh[(size_t)M_TOT * DM];
__device__ __align__(128) hf g_vh[(size_t)M_TOT * DM];
__device__ __align__(128) hf g_ah[(size_t)M_TOT * DM];
__device__ __align__(128) hf g_wh[4][(size_t)DM * DM];   // [wq;wk;wv;wo], [N,K] fp16

// ---------------- helpers ----------------
__device__ __forceinline__ uint32_t smem_u32(const void* p) {
    uint32_t a;
    asm("{ .reg .u64 t; cvta.to.shared.u64 t, %1; cvt.u32.u64 %0, t; }"
        : "=r"(a) : "l"(p));
    return a;
}
__device__ __forceinline__ uint32_t pack_h2f(float a, float b) {
    __half2 t = __floats2half2_rn(a, b);
    return *reinterpret_cast<uint32_t*>(&t);
}

#define MMAH(d, a0, a1, a2, a3, b0, b1)                                      \
    asm volatile(                                                            \
        "mma.sync.aligned.m16n8k16.row.col.f32.f16.f16.f32 "                 \
        "{%0,%1,%2,%3}, {%4,%5,%6,%7}, {%8,%9}, {%0,%1,%2,%3};"              \
        : "+f"((d)[0]), "+f"((d)[1]), "+f"((d)[2]), "+f"((d)[3])             \
        : "r"(a0), "r"(a1), "r"(a2), "r"(a3), "r"(b0), "r"(b1))

#define LDMX4(r0, r1, r2, r3, addr)                                          \
    asm volatile("ldmatrix.sync.aligned.m8n8.x4.shared.b16 "                 \
        "{%0,%1,%2,%3}, [%4];"                                               \
        : "=r"(r0), "=r"(r1), "=r"(r2), "=r"(r3) : "r"(addr))

#define LDMX4T(r0, r1, r2, r3, addr)                                         \
    asm volatile("ldmatrix.sync.aligned.m8n8.x4.trans.shared.b16 "           \
        "{%0,%1,%2,%3}, [%4];"                                               \
        : "=r"(r0), "=r"(r1), "=r"(r2), "=r"(r3) : "r"(addr))

#define CP16(dst, src)                                                       \
    asm volatile("cp.async.cg.shared.global [%0], [%1], 16;"                 \
                 :: "r"(dst), "l"(src))
#define CP_COMMIT() asm volatile("cp.async.commit_group;" ::)
#define CP_WAIT(n)  asm volatile("cp.async.wait_group %0;" :: "n"(n))

// ---------------------------------------------------------------------------
// x: fp32 -> single fp16
// ---------------------------------------------------------------------------
__global__ __launch_bounds__(256) void convert_x(
    const float* __restrict__ in, hf* __restrict__ H)
{
    size_t base = ((size_t)blockIdx.x * 256 + threadIdx.x) * 8;
    float4 v0 = *(const float4*)(in + base);
    float4 v1 = *(const float4*)(in + base + 4);
    uint4 hv;
    hv.x = pack_h2f(v0.x, v0.y); hv.y = pack_h2f(v0.z, v0.w);
    hv.z = pack_h2f(v1.x, v1.y); hv.w = pack_h2f(v1.z, v1.w);
    *(uint4*)(H + base) = hv;
}

// ---------------------------------------------------------------------------
// All 4 weights: [K,N] fp32 -> [N,K] fp16 in one launch (z = weight index)
// ---------------------------------------------------------------------------
__global__ __launch_bounds__(256) void transpose_convert4(
    const float* __restrict__ w0, const float* __restrict__ w1,
    const float* __restrict__ w2, const float* __restrict__ w3,
    hf* __restrict__ Hbase)
{
    __shared__ float t[32][33];
    const int z = blockIdx.z;
    const float* in = (z == 0) ? w0 : (z == 1) ? w1 : (z == 2) ? w2 : w3;
    hf* H = Hbase + (size_t)z * DM * DM;

    int x = blockIdx.x * 32 + threadIdx.x;
    int y = blockIdx.y * 32 + threadIdx.y;
    #pragma unroll
    for (int i = 0; i < 4; i++)
        t[threadIdx.y + i * 8][threadIdx.x] = in[(size_t)(y + i * 8) * DM + x];
    __syncthreads();
    x = blockIdx.y * 32 + threadIdx.x;
    y = blockIdx.x * 32 + threadIdx.y;
    #pragma unroll
    for (int i = 0; i < 4; i++)
        H[(size_t)(y + i * 8) * DM + x] =
            __float2half_rn(t[threadIdx.x][threadIdx.y + i * 8]);
}

// ---------------------------------------------------------------------------
// RoPE epilogue helper
// ---------------------------------------------------------------------------
__device__ __forceinline__ void rope_pair(
    int row, int col, float& v0, float& v1, float scale)
{
    int s = row & (S_LEN - 1);
    int i = (col & (HD - 1)) >> 1;
    float fraction  = (2.0f * (float)i) / (float)HD;
    float timescale = exp2f(fraction * 13.287712379549449f); // log2(10000)
    float ang = (float)s / timescale;
    float sv, cv;
    sincosf(ang, &sv, &cv);
    float r0 = (v0 * cv - v1 * sv) * scale;
    float r1 = (v1 * cv + v0 * sv) * scale;
    v0 = r0; v1 = r1;
}

// ---------------------------------------------------------------------------
// GEMM (R12 verbatim): 128x128 tile, 256 thr (8 warps 2x4), 3-stage cp.async.
// FUSED=1: B = stacked qkv weights, RoPE epilogue. FUSED=0: fp32 out.
// ---------------------------------------------------------------------------
#define GSTR   40
#define GA_EL  (128 * GSTR)
#define G1_STAGE_BYTES (2 * GA_EL * 2)          // 20480
#define GEMM1_SMEM (3 * G1_STAGE_BYTES)         // 61440

template<int FUSED>
__global__ __launch_bounds__(256, 2) void gemm_1t(
    const hf* __restrict__ A, const hf* __restrict__ B,
    hf* __restrict__ Q, hf* __restrict__ Kout, hf* __restrict__ V,
    float* __restrict__ Cf, int M, int K)
{
    extern __shared__ __align__(16) char gsm[];
    const uint32_t sb = smem_u32(gsm);

    const int tid  = threadIdx.x;
    const int lane = tid & 31;
    const int wid  = tid >> 5;
    const int warpM = wid & 1;
    const int warpN = wid >> 1;
    const int n0 = blockIdx.x * 128;
    const int m0 = blockIdx.y * 128;

    const int lm = lane & 15, lh = lane >> 4;
    const int kb_row    = (lane >> 4) * 8 + (lane & 7);
    const int kb_coladd = ((lane >> 3) & 1) * 8;

    float acc[4][4][4];
    #pragma unroll
    for (int mt = 0; mt < 4; mt++)
        #pragma unroll
        for (int nt = 0; nt < 4; nt++)
            #pragma unroll
            for (int e = 0; e < 4; e++) acc[mt][nt][e] = 0.f;

    const int NK = K / 32;

    auto issue_stage = [&](int kt) {
        const uint32_t sbase = sb + (uint32_t)(kt % 3) * G1_STAGE_BYTES;
        #pragma unroll
        for (int j = 0; j < 2; j++) {
            int idx = tid * 2 + j;
            int row = idx >> 2, ch = idx & 3;
            uint32_t doff = (uint32_t)(row * GSTR + ch * 8) * 2;
            CP16(sbase + doff,             A + (size_t)(m0 + row) * K + kt * 32 + ch * 8);
            CP16(sbase + GA_EL * 2 + doff, B + (size_t)(n0 + row) * K + kt * 32 + ch * 8);
        }
        CP_COMMIT();
    };

    issue_stage(0);
    issue_stage(1);

    for (int kt = 0; kt < NK; kt++) {
        if (kt + 1 < NK) CP_WAIT(1); else CP_WAIT(0);
        __syncthreads();
        if (kt + 2 < NK) issue_stage(kt + 2);

        const uint32_t sbase = sb + (uint32_t)(kt % 3) * G1_STAGE_BYTES;
        #pragma unroll
        for (int kc = 0; kc < 2; kc++) {
            uint32_t ah[4][4], bh[2][4];
            #pragma unroll
            for (int mt = 0; mt < 4; mt++) {
                uint32_t aaddr = sbase +
                    (uint32_t)((warpM * 64 + mt * 16 + lm) * GSTR + kc * 16 + lh * 8) * 2;
                LDMX4(ah[mt][0], ah[mt][1], ah[mt][2], ah[mt][3], aaddr);
            }
            #pragma unroll
            for (int ng = 0; ng < 2; ng++) {
                uint32_t baddr = sbase + GA_EL * 2 +
                    (uint32_t)((warpN * 32 + ng * 16 + kb_row) * GSTR + kc * 16 + kb_coladd) * 2;
                LDMX4(bh[ng][0], bh[ng][1], bh[ng][2], bh[ng][3], baddr);
            }
            #pragma unroll
            for (int mt = 0; mt < 4; mt++)
                #pragma unroll
                for (int nt = 0; nt < 4; nt++) {
                    const int ng = nt >> 1, o = (nt & 1) * 2;
                    MMAH(acc[mt][nt], ah[mt][0], ah[mt][1], ah[mt][2], ah[mt][3],
                         bh[ng][o], bh[ng][o + 1]);
                }
        }
    }

    const int mrow = lane >> 2;
    const int kcol = (lane & 3) * 2;
    if (FUSED) {
        const int which = blockIdx.x >> 4;    // 0=q, 1=k, 2=v
        hf* Ch = (which == 0) ? Q : (which == 1) ? Kout : V;
        const float qs = (which == 0) ? 0.08838834764831845f : 1.0f;
        const bool rope = (which < 2);
        #pragma unroll
        for (int mt = 0; mt < 4; mt++) {
            #pragma unroll
            for (int nt = 0; nt < 4; nt++) {
                int row = m0 + warpM * 64 + mt * 16 + mrow;
                int col = n0 + warpN * 32 + nt * 8 + kcol;
                float v0 = acc[mt][nt][0], v1 = acc[mt][nt][1];
                float v2 = acc[mt][nt][2], v3 = acc[mt][nt][3];
                if (rope) {
                    rope_pair(row,     col, v0, v1, qs);
                    rope_pair(row + 8, col, v2, v3, qs);
                }
                int cl = col & (DM - 1);
                *(uint32_t*)(Ch + (size_t)row * DM + cl)       = pack_h2f(v0, v1);
                *(uint32_t*)(Ch + (size_t)(row + 8) * DM + cl) = pack_h2f(v2, v3);
            }
        }
    } else {
        #pragma unroll
        for (int mt = 0; mt < 4; mt++) {
            #pragma unroll
            for (int nt = 0; nt < 4; nt++) {
                int row = m0 + warpM * 64 + mt * 16 + mrow;
                int col = n0 + warpN * 32 + nt * 8 + kcol;
                *(float2*)(Cf + (size_t)row * DM + col) =
                    make_float2(acc[mt][nt][0], acc[mt][nt][1]);
                *(float2*)(Cf + (size_t)(row + 8) * DM + col) =
                    make_float2(acc[mt][nt][2], acc[mt][nt][3]);
            }
        }
    }
}

// ---------------------------------------------------------------------------
// Flash attention v7: 128-row q tiles, 8 warps, K-tiles of 128 keys.
// Halves barriers / softmax reductions / rescales per key vs 64-key tiles.
// ---------------------------------------------------------------------------
#define FSTR    136
#define F_Q     0
#define F_KV0   (128 * FSTR)
#define F_KVSZ  (2 * 128 * FSTR)
#define V_OFF   (128 * FSTR)
#define FLASH_SMEM_BYTES ((F_KV0 + 2 * F_KVSZ) * 2)   // 174080

__global__ __launch_bounds__(256, 1) void flash_tc7(
    const hf* __restrict__ Qh, const hf* __restrict__ Kh,
    const hf* __restrict__ Vh, hf* __restrict__ Oh)
{
    extern __shared__ __align__(16) char fsm[];
    const uint32_t sb = smem_u32(fsm);

    const int tid  = threadIdx.x;
    const int lane = tid & 31;
    const int w    = tid >> 5;
    const int qt   = blockIdx.x;
    const int hN   = blockIdx.y;
    const int b    = blockIdx.z;
    const int q0   = qt * 128;
    const size_t head = (size_t)hN * HD;

    auto issue_kv = [&](int kt, int st) {
        const int k0 = kt * 128;
        const uint32_t base = sb + (F_KV0 + st * F_KVSZ) * 2;
        #pragma unroll
        for (int i = 0; i < 8; i++) {
            int idx = tid + i * 256;              // 0..2047
            int row = idx >> 4, ch = idx & 15;
            uint32_t doff = (uint32_t)(row * FSTR + ch * 8) * 2;
            size_t g = ((size_t)(b * S_LEN + k0 + row)) * DM + head + ch * 8;
            CP16(base + doff,             Kh + g);
            CP16(base + V_OFF * 2 + doff, Vh + g);
        }
        CP_COMMIT();
    };

    // Q tile 128x128
    #pragma unroll
    for (int i = 0; i < 8; i++) {
        int idx = tid + i * 256;
        int row = idx >> 4, ch = idx & 15;
        uint32_t doff = (uint32_t)(row * FSTR + ch * 8) * 2;
        size_t g = ((size_t)(b * S_LEN + q0 + row)) * DM + head + ch * 8;
        CP16(sb + doff, Qh + g);
    }
    issue_kv(0, 0);

    float m0 = -1e30f, m1 = -1e30f, l0 = 0.f, l1 = 0.f;
    float o[16][4];
    #pragma unroll
    for (int t = 0; t < 16; t++)
        #pragma unroll
        for (int e = 0; e < 4; e++) o[t][e] = 0.f;

    const int ktiles = qt + 1;              // 128-key tiles

    const uint32_t qa_base =
        sb + ((w * 16 + (lane & 15)) * FSTR + (lane >> 4) * 8) * 2;
    const uint32_t kb_row    = (lane >> 4) * 8 + (lane & 7);
    const uint32_t kb_coladd = ((lane >> 3) & 1) * 8;
    const uint32_t vb_rowadd = ((lane >> 3) & 1) * 8 + (lane & 7);
    const uint32_t vb_coladd = (lane >> 4) * 8;

    for (int kt = 0; kt < ktiles; kt++) {
        const int st = kt & 1;
        CP_WAIT(0);                         // tile kt (and Q on kt=0) landed
        __syncthreads();                    // all warps done with buf st^1
        if (kt + 1 < ktiles) issue_kv(kt + 1, st ^ 1);

        const uint32_t khb = F_KV0 + st * F_KVSZ;
        const uint32_t vhb = khb + V_OFF;

        // ---- S = Q K^T  (m16 x n128 per warp) ----
        float c[16][4];
        #pragma unroll
        for (int t = 0; t < 16; t++)
            #pragma unroll
            for (int e = 0; e < 4; e++) c[t][e] = 0.f;

        #pragma unroll
        for (int kc = 0; kc < 8; kc++) {
            uint32_t a0, a1, a2, a3;
            LDMX4(a0, a1, a2, a3, qa_base + kc * 32);
            #pragma unroll
            for (int tp = 0; tp < 8; tp++) {
                uint32_t b0, b1, b2, b3;
                uint32_t kaddr = sb +
                    (khb + (tp * 16 + kb_row) * FSTR + kc * 16 + kb_coladd) * 2;
                LDMX4(b0, b1, b2, b3, kaddr);
                MMAH(c[2*tp],   a0, a1, a2, a3, b0, b1);
                MMAH(c[2*tp+1], a0, a1, a2, a3, b2, b3);
            }
        }

        // ---- causal mask (diagonal tile: kt == qt) ----
        const int rowg0 = q0 + w * 16 + (lane >> 2);
        if (kt == qt) {
            const int k0 = kt * 128;
            #pragma unroll
            for (int t = 0; t < 16; t++) {
                int colb = k0 + t * 8 + (lane & 3) * 2;
                if (colb     > rowg0)     c[t][0] = -1e30f;
                if (colb + 1 > rowg0)     c[t][1] = -1e30f;
                if (colb     > rowg0 + 8) c[t][2] = -1e30f;
                if (colb + 1 > rowg0 + 8) c[t][3] = -1e30f;
            }
        }

        // ---- online softmax (one pass per 128 keys) ----
        float mx0 = -1e30f, mx1 = -1e30f;
        #pragma unroll
        for (int t = 0; t < 16; t++) {
            mx0 = fmaxf(mx0, fmaxf(c[t][0], c[t][1]));
            mx1 = fmaxf(mx1, fmaxf(c[t][2], c[t][3]));
        }
        mx0 = fmaxf(mx0, __shfl_xor_sync(0xffffffffu, mx0, 1));
        mx0 = fmaxf(mx0, __shfl_xor_sync(0xffffffffu, mx0, 2));
        mx1 = fmaxf(mx1, __shfl_xor_sync(0xffffffffu, mx1, 1));
        mx1 = fmaxf(mx1, __shfl_xor_sync(0xffffffffu, mx1, 2));
        const float mn0 = fmaxf(m0, mx0);
        const float mn1 = fmaxf(m1, mx1);
        const float sc0 = __expf(m0 - mn0);
        const float sc1 = __expf(m1 - mn1);
        float sum0 = 0.f, sum1 = 0.f;
        #pragma unroll
        for (int t = 0; t < 16; t++) {
            c[t][0] = __expf(c[t][0] - mn0); sum0 += c[t][0];
            c[t][1] = __expf(c[t][1] - mn0); sum0 += c[t][1];
            c[t][2] = __expf(c[t][2] - mn1); sum1 += c[t][2];
            c[t][3] = __expf(c[t][3] - mn1); sum1 += c[t][3];
        }
        sum0 += __shfl_xor_sync(0xffffffffu, sum0, 1);
        sum0 += __shfl_xor_sync(0xffffffffu, sum0, 2);
        sum1 += __shfl_xor_sync(0xffffffffu, sum1, 1);
        sum1 += __shfl_xor_sync(0xffffffffu, sum1, 2);
        m0 = mn0; m1 = mn1;
        l0 = l0 * sc0 + sum0;
        l1 = l1 * sc1 + sum1;
        #pragma unroll
        for (int t = 0; t < 16; t++) {
            o[t][0] *= sc0; o[t][1] *= sc0;
            o[t][2] *= sc1; o[t][3] *= sc1;
        }

        // ---- O += P V  (k = 128 keys) ----
        #pragma unroll
        for (int kc = 0; kc < 8; kc++) {
            uint32_t pa[4];
            #pragma unroll
            for (int half = 0; half < 2; half++) {
                const int t = 2 * kc + half;
                pa[2*half]   = pack_h2f(c[t][0], c[t][1]);
                pa[2*half+1] = pack_h2f(c[t][2], c[t][3]);
            }
            #pragma unroll
            for (int tp = 0; tp < 8; tp++) {
                uint32_t v0, v1, v2, v3;
                uint32_t vaddr = sb +
                    (vhb + (kc * 16 + vb_rowadd) * FSTR + tp * 16 + vb_coladd) * 2;
                LDMX4T(v0, v1, v2, v3, vaddr);
                MMAH(o[2*tp],   pa[0], pa[1], pa[2], pa[3], v0, v1);
                MMAH(o[2*tp+1], pa[0], pa[1], pa[2], pa[3], v2, v3);
            }
        }
    }

    // ---- normalize + store ----
    const float inv0 = 1.0f / l0;
    const float inv1 = 1.0f / l1;
    const int rowg = q0 + w * 16 + (lane >> 2);
    #pragma unroll
    for (int t = 0; t < 16; t++) {
        size_t g0 = ((size_t)(b * S_LEN + rowg)) * DM + head + t * 8 + (lane & 3) * 2;
        size_t g1 = g0 + 8 * DM;
        *(uint32_t*)(Oh + g0) = pack_h2f(o[t][0] * inv0, o[t][1] * inv0);
        *(uint32_t*)(Oh + g1) = pack_h2f(o[t][2] * inv1, o[t][3] * inv1);
    }
}

// ---------------------------------------------------------------------------
extern "C" void kernel_launch(void* const* d_in, const int* in_sizes, int n_in,
                              void* d_out, int out_size)
{
    const float* x  = (const float*)d_in[0];
    const float* wq = (const float*)d_in[1];
    const float* wk = (const float*)d_in[2];
    const float* wv = (const float*)d_in[3];
    const float* wo = (const float*)d_in[4];
    float* out = (float*)d_out;

    hf *xh, *qh, *kh, *vh, *ah, *wh;
    cudaGetSymbolAddress((void**)&xh, g_xh);
    cudaGetSymbolAddress((void**)&qh, g_qh);
    cudaGetSymbolAddress((void**)&kh, g_kh);
    cudaGetSymbolAddress((void**)&vh, g_vh);
    cudaGetSymbolAddress((void**)&ah, g_ah);
    cudaGetSymbolAddress((void**)&wh, g_wh);
    const size_t WSZ = (size_t)DM * DM;

    convert_x<<<(M_TOT * (size_t)DM) / (256 * 8), 256>>>(x, xh);
    dim3 tgrid(DM / 32, DM / 32, 4), tblk(32, 8);
    transpose_convert4<<<tgrid, tblk>>>(wq, wk, wv, wo, wh);

    cudaFuncSetAttribute(gemm_1t<0>, cudaFuncAttributeMaxDynamicSharedMemorySize,
                         GEMM1_SMEM);
    cudaFuncSetAttribute(gemm_1t<1>, cudaFuncAttributeMaxDynamicSharedMemorySize,
                         GEMM1_SMEM);

    // Fused QKV projection + RoPE epilogue: N = 3*2048, one launch
    dim3 qkvgrid(3 * DM / 128, M_TOT / 128);
    gemm_1t<1><<<qkvgrid, 256, GEMM1_SMEM>>>(xh, wh, qh, kh, vh, nullptr,
                                             M_TOT, DM);

    cudaFuncSetAttribute(flash_tc7, cudaFuncAttributeMaxDynamicSharedMemorySize,
                         FLASH_SMEM_BYTES);
    dim3 fgrid(S_LEN / 128, NH, B_SZ);
    flash_tc7<<<fgrid, 256, FLASH_SMEM_BYTES>>>(qh, kh, vh, ah);

    // Out-proj: fp32 output
    dim3 ogrid(DM / 128, M_TOT / 128);
    gemm_1t<0><<<ogrid, 256, GEMM1_SMEM>>>(ah, wh + 3 * WSZ, nullptr, nullptr,
                                           nullptr, out, M_TOT, DM);
}

// round 16
// speedup vs baseline: 1.4410x; 1.1819x over previous
#include <cuda_runtime.h>
#include <cuda_fp16.h>
#include <cstdint>
#include <math.h>

#define B_SZ   4
#define S_LEN  2048
#define NH     16
#define HD     128
#define DM     2048
#define M_TOT  (B_SZ * S_LEN)
typedef __half hf;

// ---------------- scratch (device globals; allocation-free) ----------------
__device__ __align__(128) hf g_xh[(size_t)M_TOT * DM];
__device__ __align__(128) hf g_qh[(size_t)M_TOT * DM];
__device__ __align__(128) hf g_kh[(size_t)M_TOT * DM];
__device__ __align__(128) hf g_vh[(size_t)M_TOT * DM];
__device__ __align__(128) hf g_ah[(size_t)M_TOT * DM];
__device__ __align__(128) hf g_wh[4][(size_t)DM * DM];   // [wq;wk;wv;wo], [N,K] fp16

// ---------------- helpers ----------------
__device__ __forceinline__ uint32_t smem_u32(const void* p) {
    uint32_t a;
    asm("{ .reg .u64 t; cvta.to.shared.u64 t, %1; cvt.u32.u64 %0, t; }"
        : "=r"(a) : "l"(p));
    return a;
}
__device__ __forceinline__ uint32_t pack_h2f(float a, float b) {
    __half2 t = __floats2half2_rn(a, b);
    return *reinterpret_cast<uint32_t*>(&t);
}

#define MMAH(d, a0, a1, a2, a3, b0, b1)                                      \
    asm volatile(                                                            \
        "mma.sync.aligned.m16n8k16.row.col.f32.f16.f16.f32 "                 \
        "{%0,%1,%2,%3}, {%4,%5,%6,%7}, {%8,%9}, {%0,%1,%2,%3};"              \
        : "+f"((d)[0]), "+f"((d)[1]), "+f"((d)[2]), "+f"((d)[3])             \
        : "r"(a0), "r"(a1), "r"(a2), "r"(a3), "r"(b0), "r"(b1))

#define LDMX4(r0, r1, r2, r3, addr)                                          \
    asm volatile("ldmatrix.sync.aligned.m8n8.x4.shared.b16 "                 \
        "{%0,%1,%2,%3}, [%4];"                                               \
        : "=r"(r0), "=r"(r1), "=r"(r2), "=r"(r3) : "r"(addr))

#define LDMX4T(r0, r1, r2, r3, addr)                                         \
    asm volatile("ldmatrix.sync.aligned.m8n8.x4.trans.shared.b16 "           \
        "{%0,%1,%2,%3}, [%4];"                                               \
        : "=r"(r0), "=r"(r1), "=r"(r2), "=r"(r3) : "r"(addr))

#define CP16(dst, src)                                                       \
    asm volatile("cp.async.cg.shared.global [%0], [%1], 16;"                 \
                 :: "r"(dst), "l"(src))
#define CP_COMMIT() asm volatile("cp.async.commit_group;" ::)
#define CP_WAIT(n)  asm volatile("cp.async.wait_group %0;" :: "n"(n))

// ---------------------------------------------------------------------------
// x: fp32 -> single fp16
// ---------------------------------------------------------------------------
__global__ __launch_bounds__(256) void convert_x(
    const float* __restrict__ in, hf* __restrict__ H)
{
    size_t base = ((size_t)blockIdx.x * 256 + threadIdx.x) * 8;
    float4 v0 = *(const float4*)(in + base);
    float4 v1 = *(const float4*)(in + base + 4);
    uint4 hv;
    hv.x = pack_h2f(v0.x, v0.y); hv.y = pack_h2f(v0.z, v0.w);
    hv.z = pack_h2f(v1.x, v1.y); hv.w = pack_h2f(v1.z, v1.w);
    *(uint4*)(H + base) = hv;
}

// ---------------------------------------------------------------------------
// All 4 weights: [K,N] fp32 -> [N,K] fp16 in one launch (z = weight index)
// ---------------------------------------------------------------------------
__global__ __launch_bounds__(256) void transpose_convert4(
    const float* __restrict__ w0, const float* __restrict__ w1,
    const float* __restrict__ w2, const float* __restrict__ w3,
    hf* __restrict__ Hbase)
{
    __shared__ float t[32][33];
    const int z = blockIdx.z;
    const float* in = (z == 0) ? w0 : (z == 1) ? w1 : (z == 2) ? w2 : w3;
    hf* H = Hbase + (size_t)z * DM * DM;

    int x = blockIdx.x * 32 + threadIdx.x;
    int y = blockIdx.y * 32 + threadIdx.y;
    #pragma unroll
    for (int i = 0; i < 4; i++)
        t[threadIdx.y + i * 8][threadIdx.x] = in[(size_t)(y + i * 8) * DM + x];
    __syncthreads();
    x = blockIdx.y * 32 + threadIdx.x;
    y = blockIdx.x * 32 + threadIdx.y;
    #pragma unroll
    for (int i = 0; i < 4; i++)
        H[(size_t)(y + i * 8) * DM + x] =
            __float2half_rn(t[threadIdx.x][threadIdx.y + i * 8]);
}

// ---------------------------------------------------------------------------
// RoPE epilogue helper
// ---------------------------------------------------------------------------
__device__ __forceinline__ void rope_pair(
    int row, int col, float& v0, float& v1, float scale)
{
    int s = row & (S_LEN - 1);
    int i = (col & (HD - 1)) >> 1;
    float fraction  = (2.0f * (float)i) / (float)HD;
    float timescale = exp2f(fraction * 13.287712379549449f); // log2(10000)
    float ang = (float)s / timescale;
    float sv, cv;
    sincosf(ang, &sv, &cv);
    float r0 = (v0 * cv - v1 * sv) * scale;
    float r1 = (v1 * cv + v0 * sv) * scale;
    v0 = r0; v1 = r1;
}

// ---------------------------------------------------------------------------
// GEMM v5: 128x128 tile, 256 thr (8 warps 2x4), K-chunk 64, 3-stage cp.async.
// Half the barriers / pipeline turns of the K32 version; 2 CTAs/SM.
// FUSED=1: B = stacked qkv weights, RoPE epilogue. FUSED=0: fp32 out.
// ---------------------------------------------------------------------------
#define GSTR   72
#define GA_EL  (128 * GSTR)                     // 9216 elems
#define G1_STAGE_BYTES (2 * GA_EL * 2)          // 36864
#define GEMM1_SMEM (3 * G1_STAGE_BYTES)         // 110592

template<int FUSED>
__global__ __launch_bounds__(256, 2) void gemm_k64(
    const hf* __restrict__ A, const hf* __restrict__ B,
    hf* __restrict__ Q, hf* __restrict__ Kout, hf* __restrict__ V,
    float* __restrict__ Cf, int M, int K)
{
    extern __shared__ __align__(16) char gsm[];
    const uint32_t sb = smem_u32(gsm);

    const int tid  = threadIdx.x;
    const int lane = tid & 31;
    const int wid  = tid >> 5;
    const int warpM = wid & 1;
    const int warpN = wid >> 1;
    const int n0 = blockIdx.x * 128;
    const int m0 = blockIdx.y * 128;

    const int lm = lane & 15, lh = lane >> 4;
    const int kb_row    = (lane >> 4) * 8 + (lane & 7);
    const int kb_coladd = ((lane >> 3) & 1) * 8;

    float acc[4][4][4];
    #pragma unroll
    for (int mt = 0; mt < 4; mt++)
        #pragma unroll
        for (int nt = 0; nt < 4; nt++)
            #pragma unroll
            for (int e = 0; e < 4; e++) acc[mt][nt][e] = 0.f;

    const int NK = K / 64;

    // loader: 4 chunks of 16B per thread per array (128 rows x 8 chunks)
    auto issue_stage = [&](int kt) {
        const uint32_t sbase = sb + (uint32_t)(kt % 3) * G1_STAGE_BYTES;
        #pragma unroll
        for (int j = 0; j < 4; j++) {
            int idx = tid + j * 256;            // 0..1023
            int row = idx >> 3, ch = idx & 7;
            uint32_t doff = (uint32_t)(row * GSTR + ch * 8) * 2;
            CP16(sbase + doff,             A + (size_t)(m0 + row) * K + kt * 64 + ch * 8);
            CP16(sbase + GA_EL * 2 + doff, B + (size_t)(n0 + row) * K + kt * 64 + ch * 8);
        }
        CP_COMMIT();
    };

    issue_stage(0);
    issue_stage(1);

    for (int kt = 0; kt < NK; kt++) {
        if (kt + 1 < NK) CP_WAIT(1); else CP_WAIT(0);
        __syncthreads();
        if (kt + 2 < NK) issue_stage(kt + 2);

        const uint32_t sbase = sb + (uint32_t)(kt % 3) * G1_STAGE_BYTES;
        #pragma unroll
        for (int kc = 0; kc < 4; kc++) {
            uint32_t ah[4][4], bh[2][4];
            #pragma unroll
            for (int mt = 0; mt < 4; mt++) {
                uint32_t aaddr = sbase +
                    (uint32_t)((warpM * 64 + mt * 16 + lm) * GSTR + kc * 16 + lh * 8) * 2;
                LDMX4(ah[mt][0], ah[mt][1], ah[mt][2], ah[mt][3], aaddr);
            }
            #pragma unroll
            for (int ng = 0; ng < 2; ng++) {
                uint32_t baddr = sbase + GA_EL * 2 +
                    (uint32_t)((warpN * 32 + ng * 16 + kb_row) * GSTR + kc * 16 + kb_coladd) * 2;
                LDMX4(bh[ng][0], bh[ng][1], bh[ng][2], bh[ng][3], baddr);
            }
            #pragma unroll
            for (int mt = 0; mt < 4; mt++)
                #pragma unroll
                for (int nt = 0; nt < 4; nt++) {
                    const int ng = nt >> 1, o = (nt & 1) * 2;
                    MMAH(acc[mt][nt], ah[mt][0], ah[mt][1], ah[mt][2], ah[mt][3],
                         bh[ng][o], bh[ng][o + 1]);
                }
        }
    }

    const int mrow = lane >> 2;
    const int kcol = (lane & 3) * 2;
    if (FUSED) {
        const int which = blockIdx.x >> 4;    // 0=q, 1=k, 2=v
        hf* Ch = (which == 0) ? Q : (which == 1) ? Kout : V;
        const float qs = (which == 0) ? 0.08838834764831845f : 1.0f;
        const bool rope = (which < 2);
        #pragma unroll
        for (int mt = 0; mt < 4; mt++) {
            #pragma unroll
            for (int nt = 0; nt < 4; nt++) {
                int row = m0 + warpM * 64 + mt * 16 + mrow;
                int col = n0 + warpN * 32 + nt * 8 + kcol;
                float v0 = acc[mt][nt][0], v1 = acc[mt][nt][1];
                float v2 = acc[mt][nt][2], v3 = acc[mt][nt][3];
                if (rope) {
                    rope_pair(row,     col, v0, v1, qs);
                    rope_pair(row + 8, col, v2, v3, qs);
                }
                int cl = col & (DM - 1);
                *(uint32_t*)(Ch + (size_t)row * DM + cl)       = pack_h2f(v0, v1);
                *(uint32_t*)(Ch + (size_t)(row + 8) * DM + cl) = pack_h2f(v2, v3);
            }
        }
    } else {
        #pragma unroll
        for (int mt = 0; mt < 4; mt++) {
            #pragma unroll
            for (int nt = 0; nt < 4; nt++) {
                int row = m0 + warpM * 64 + mt * 16 + mrow;
                int col = n0 + warpN * 32 + nt * 8 + kcol;
                *(float2*)(Cf + (size_t)row * DM + col) =
                    make_float2(acc[mt][nt][0], acc[mt][nt][1]);
                *(float2*)(Cf + (size_t)(row + 8) * DM + col) =
                    make_float2(acc[mt][nt][2], acc[mt][nt][3]);
            }
        }
    }
}

// ---------------------------------------------------------------------------
// Flash attention v7 (R15, 262us): 128-row q tiles, 8 warps, 128-key K-tiles.
// ---------------------------------------------------------------------------
#define FSTR    136
#define F_Q     0
#define F_KV0   (128 * FSTR)
#define F_KVSZ  (2 * 128 * FSTR)
#define V_OFF   (128 * FSTR)
#define FLASH_SMEM_BYTES ((F_KV0 + 2 * F_KVSZ) * 2)   // 174080

__global__ __launch_bounds__(256, 1) void flash_tc7(
    const hf* __restrict__ Qh, const hf* __restrict__ Kh,
    const hf* __restrict__ Vh, hf* __restrict__ Oh)
{
    extern __shared__ __align__(16) char fsm[];
    const uint32_t sb = smem_u32(fsm);

    const int tid  = threadIdx.x;
    const int lane = tid & 31;
    const int w    = tid >> 5;
    const int qt   = blockIdx.x;
    const int hN   = blockIdx.y;
    const int b    = blockIdx.z;
    const int q0   = qt * 128;
    const size_t head = (size_t)hN * HD;

    auto issue_kv = [&](int kt, int st) {
        const int k0 = kt * 128;
        const uint32_t base = sb + (F_KV0 + st * F_KVSZ) * 2;
        #pragma unroll
        for (int i = 0; i < 8; i++) {
            int idx = tid + i * 256;
            int row = idx >> 4, ch = idx & 15;
            uint32_t doff = (uint32_t)(row * FSTR + ch * 8) * 2;
            size_t g = ((size_t)(b * S_LEN + k0 + row)) * DM + head + ch * 8;
            CP16(base + doff,             Kh + g);
            CP16(base + V_OFF * 2 + doff, Vh + g);
        }
        CP_COMMIT();
    };

    #pragma unroll
    for (int i = 0; i < 8; i++) {
        int idx = tid + i * 256;
        int row = idx >> 4, ch = idx & 15;
        uint32_t doff = (uint32_t)(row * FSTR + ch * 8) * 2;
        size_t g = ((size_t)(b * S_LEN + q0 + row)) * DM + head + ch * 8;
        CP16(sb + doff, Qh + g);
    }
    issue_kv(0, 0);

    float m0 = -1e30f, m1 = -1e30f, l0 = 0.f, l1 = 0.f;
    float o[16][4];
    #pragma unroll
    for (int t = 0; t < 16; t++)
        #pragma unroll
        for (int e = 0; e < 4; e++) o[t][e] = 0.f;

    const int ktiles = qt + 1;

    const uint32_t qa_base =
        sb + ((w * 16 + (lane & 15)) * FSTR + (lane >> 4) * 8) * 2;
    const uint32_t kb_row    = (lane >> 4) * 8 + (lane & 7);
    const uint32_t kb_coladd = ((lane >> 3) & 1) * 8;
    const uint32_t vb_rowadd = ((lane >> 3) & 1) * 8 + (lane & 7);
    const uint32_t vb_coladd = (lane >> 4) * 8;

    for (int kt = 0; kt < ktiles; kt++) {
        const int st = kt & 1;
        CP_WAIT(0);
        __syncthreads();
        if (kt + 1 < ktiles) issue_kv(kt + 1, st ^ 1);

        const uint32_t khb = F_KV0 + st * F_KVSZ;
        const uint32_t vhb = khb + V_OFF;

        float c[16][4];
        #pragma unroll
        for (int t = 0; t < 16; t++)
            #pragma unroll
            for (int e = 0; e < 4; e++) c[t][e] = 0.f;

        #pragma unroll
        for (int kc = 0; kc < 8; kc++) {
            uint32_t a0, a1, a2, a3;
            LDMX4(a0, a1, a2, a3, qa_base + kc * 32);
            #pragma unroll
            for (int tp = 0; tp < 8; tp++) {
                uint32_t b0, b1, b2, b3;
                uint32_t kaddr = sb +
                    (khb + (tp * 16 + kb_row) * FSTR + kc * 16 + kb_coladd) * 2;
                LDMX4(b0, b1, b2, b3, kaddr);
                MMAH(c[2*tp],   a0, a1, a2, a3, b0, b1);
                MMAH(c[2*tp+1], a0, a1, a2, a3, b2, b3);
            }
        }

        const int rowg0 = q0 + w * 16 + (lane >> 2);
        if (kt == qt) {
            const int k0 = kt * 128;
            #pragma unroll
            for (int t = 0; t < 16; t++) {
                int colb = k0 + t * 8 + (lane & 3) * 2;
                if (colb     > rowg0)     c[t][0] = -1e30f;
                if (colb + 1 > rowg0)     c[t][1] = -1e30f;
                if (colb     > rowg0 + 8) c[t][2] = -1e30f;
                if (colb + 1 > rowg0 + 8) c[t][3] = -1e30f;
            }
        }

        float mx0 = -1e30f, mx1 = -1e30f;
        #pragma unroll
        for (int t = 0; t < 16; t++) {
            mx0 = fmaxf(mx0, fmaxf(c[t][0], c[t][1]));
            mx1 = fmaxf(mx1, fmaxf(c[t][2], c[t][3]));
        }
        mx0 = fmaxf(mx0, __shfl_xor_sync(0xffffffffu, mx0, 1));
        mx0 = fmaxf(mx0, __shfl_xor_sync(0xffffffffu, mx0, 2));
        mx1 = fmaxf(mx1, __shfl_xor_sync(0xffffffffu, mx1, 1));
        mx1 = fmaxf(mx1, __shfl_xor_sync(0xffffffffu, mx1, 2));
        const float mn0 = fmaxf(m0, mx0);
        const float mn1 = fmaxf(m1, mx1);
        const float sc0 = __expf(m0 - mn0);
        const float sc1 = __expf(m1 - mn1);
        float sum0 = 0.f, sum1 = 0.f;
        #pragma unroll
        for (int t = 0; t < 16; t++) {
            c[t][0] = __expf(c[t][0] - mn0); sum0 += c[t][0];
            c[t][1] = __expf(c[t][1] - mn0); sum0 += c[t][1];
            c[t][2] = __expf(c[t][2] - mn1); sum1 += c[t][2];
            c[t][3] = __expf(c[t][3] - mn1); sum1 += c[t][3];
        }
        sum0 += __shfl_xor_sync(0xffffffffu, sum0, 1);
        sum0 += __shfl_xor_sync(0xffffffffu, sum0, 2);
        sum1 += __shfl_xor_sync(0xffffffffu, sum1, 1);
        sum1 += __shfl_xor_sync(0xffffffffu, sum1, 2);
        m0 = mn0; m1 = mn1;
        l0 = l0 * sc0 + sum0;
        l1 = l1 * sc1 + sum1;
        #pragma unroll
        for (int t = 0; t < 16; t++) {
            o[t][0] *= sc0; o[t][1] *= sc0;
            o[t][2] *= sc1; o[t][3] *= sc1;
        }

        #pragma unroll
        for (int kc = 0; kc < 8; kc++) {
            uint32_t pa[4];
            #pragma unroll
            for (int half = 0; half < 2; half++) {
                const int t = 2 * kc + half;
                pa[2*half]   = pack_h2f(c[t][0], c[t][1]);
                pa[2*half+1] = pack_h2f(c[t][2], c[t][3]);
            }
            #pragma unroll
            for (int tp = 0; tp < 8; tp++) {
                uint32_t v0, v1, v2, v3;
                uint32_t vaddr = sb +
                    (vhb + (kc * 16 + vb_rowadd) * FSTR + tp * 16 + vb_coladd) * 2;
                LDMX4T(v0, v1, v2, v3, vaddr);
                MMAH(o[2*tp],   pa[0], pa[1], pa[2], pa[3], v0, v1);
                MMAH(o[2*tp+1], pa[0], pa[1], pa[2], pa[3], v2, v3);
            }
        }
    }

    const float inv0 = 1.0f / l0;
    const float inv1 = 1.0f / l1;
    const int rowg = q0 + w * 16 + (lane >> 2);
    #pragma unroll
    for (int t = 0; t < 16; t++) {
        size_t g0 = ((size_t)(b * S_LEN + rowg)) * DM + head + t * 8 + (lane & 3) * 2;
        size_t g1 = g0 + 8 * DM;
        *(uint32_t*)(Oh + g0) = pack_h2f(o[t][0] * inv0, o[t][1] * inv0);
        *(uint32_t*)(Oh + g1) = pack_h2f(o[t][2] * inv1, o[t][3] * inv1);
    }
}

// ---------------------------------------------------------------------------
extern "C" void kernel_launch(void* const* d_in, const int* in_sizes, int n_in,
                              void* d_out, int out_size)
{
    const float* x  = (const float*)d_in[0];
    const float* wq = (const float*)d_in[1];
    const float* wk = (const float*)d_in[2];
    const float* wv = (const float*)d_in[3];
    const float* wo = (const float*)d_in[4];
    float* out = (float*)d_out;

    hf *xh, *qh, *kh, *vh, *ah, *wh;
    cudaGetSymbolAddress((void**)&xh, g_xh);
    cudaGetSymbolAddress((void**)&qh, g_qh);
    cudaGetSymbolAddress((void**)&kh, g_kh);
    cudaGetSymbolAddress((void**)&vh, g_vh);
    cudaGetSymbolAddress((void**)&ah, g_ah);
    cudaGetSymbolAddress((void**)&wh, g_wh);
    const size_t WSZ = (size_t)DM * DM;

    convert_x<<<(M_TOT * (size_t)DM) / (256 * 8), 256>>>(x, xh);
    dim3 tgrid(DM / 32, DM / 32, 4), tblk(32, 8);
    transpose_convert4<<<tgrid, tblk>>>(wq, wk, wv, wo, wh);

    cudaFuncSetAttribute(gemm_k64<0>, cudaFuncAttributeMaxDynamicSharedMemorySize,
                         GEMM1_SMEM);
    cudaFuncSetAttribute(gemm_k64<1>, cudaFuncAttributeMaxDynamicSharedMemorySize,
                         GEMM1_SMEM);

    // Fused QKV projection + RoPE epilogue: N = 3*2048, one launch
    dim3 qkvgrid(3 * DM / 128, M_TOT / 128);
    gemm_k64<1><<<qkvgrid, 256, GEMM1_SMEM>>>(xh, wh, qh, kh, vh, nullptr,
                                              M_TOT, DM);

    cudaFuncSetAttribute(flash_tc7, cudaFuncAttributeMaxDynamicSharedMemorySize,
                         FLASH_SMEM_BYTES);
    dim3 fgrid(S_LEN / 128, NH, B_SZ);
    flash_tc7<<<fgrid, 256, FLASH_SMEM_BYTES>>>(qh, kh, vh, ah);

    // Out-proj: fp32 output
    dim3 ogrid(DM / 128, M_TOT / 128);
    gemm_k64<0><<<ogrid, 256, GEMM1_SMEM>>>(ah, wh + 3 * WSZ, nullptr, nullptr,
                                            nullptr, out, M_TOT, DM);
}